// round 8
// baseline (speedup 1.0000x reference)
#include <cuda_runtime.h>
#include <cuda_bf16.h>
#include <math.h>

#define FULL_MASK 0xffffffffu
#define AP 24   // smem row pitch in bf16 elems (48B) -> conflict-free ldmatrix

// ---------------- scratch (__device__ globals; no runtime allocation) -------
__device__ __align__(16) __nv_bfloat16 g_q[32u*1024u*32u];  // [bf][t][c], pre-scaled by 0.25*log2(e)
__device__ __align__(16) __nv_bfloat16 g_k[8u*1024u*32u];   // [b][s][c]
__device__ __align__(16) __nv_bfloat16 g_v[8u*1024u*32u];   // [b][s][c]
__device__ __align__(16) float          g_y[32u*1024u*32u]; // attention output, fp32

__device__ __forceinline__ float gelu_exact(float v) {
    return 0.5f * v * (1.f + erff(v * 0.70710678118654752440f));
}
__device__ __forceinline__ float ex2(float x) {
    float y; asm("ex2.approx.f32 %0, %1;" : "=f"(y) : "f"(x)); return y;
}

// ======================= merged TCL for q, k, v ==============================
// grid (16, 48): y<32 -> q (causal seq y), y<40 -> k (past seq y-32), else v.
__global__ void __launch_bounds__(64) tcl_all_kernel(
    const float* __restrict__ causal, const float* __restrict__ past,
    const float* __restrict__ wq_c, const float* __restrict__ bq_c,
    const float* __restrict__ wq_p, const float* __restrict__ bq_p,
    const float* __restrict__ wk_c, const float* __restrict__ bk_c,
    const float* __restrict__ wk_p, const float* __restrict__ bk_p,
    const float* __restrict__ wv_c, const float* __restrict__ bv_c,
    const float* __restrict__ wv_p, const float* __restrict__ bv_p)
{
    __shared__ alignas(16) float sW[32*3*64];   // [ci][k][j] (j contiguous)
    __shared__ alignas(16) float sWp[64*32];    // [j][c]     (c contiguous)
    __shared__ float sB[64];
    __shared__ float sBp[32];
    __shared__ float sx[66][33];                // pitch 33 -> conflict-free column reads
    const int T = 1024;
    int ny = blockIdx.y, t0 = blockIdx.x * 64, tid = threadIdx.x;

    const float *x, *wconv, *bconv, *wproj, *bproj;
    __nv_bfloat16* out;
    float scale;
    int n;
    if (ny < 32) {
        x = causal; n = ny; out = g_q;
        wconv = wq_c; bconv = bq_c; wproj = wq_p; bproj = bq_p;
        scale = 0.36067376022224085f;   // (1/sqrt(16)) * log2(e)
    } else if (ny < 40) {
        x = past; n = ny - 32; out = g_k;
        wconv = wk_c; bconv = bk_c; wproj = wk_p; bproj = bk_p;
        scale = 1.0f;
    } else {
        x = past; n = ny - 40; out = g_v;
        wconv = wv_c; bconv = bv_c; wproj = wv_p; bproj = bv_p;
        scale = 1.0f;
    }

    for (int i = tid; i < 6144; i += 64) {
        int j = i / 96, r = i - j * 96, ci = r / 3, kk = r - ci * 3;
        sW[(ci*3 + kk)*64 + j] = wconv[i];
    }
    for (int i = tid; i < 2048; i += 64) {
        int c = i >> 6, j = i & 63;
        sWp[j*32 + c] = wproj[i];
    }
    sB[tid] = bconv[tid];
    if (tid < 32) sBp[tid] = bproj[tid];
    for (int i = tid; i < 66*32; i += 64) {
        int r = i >> 5, c = i & 31;
        int t = t0 - 2 + r;
        sx[r][c] = (t >= 0) ? x[((size_t)n*T + t)*32 + c] : 0.f;
    }
    __syncthreads();

    float acc[64];
    #pragma unroll
    for (int j = 0; j < 64; j++) acc[j] = sB[j];

    #pragma unroll 1
    for (int ci = 0; ci < 32; ci++) {
        float x0 = sx[tid + 0][ci];
        float x1 = sx[tid + 1][ci];
        float x2 = sx[tid + 2][ci];
        const float4* w0 = (const float4*)&sW[(ci*3 + 0)*64];
        const float4* w1 = (const float4*)&sW[(ci*3 + 1)*64];
        const float4* w2 = (const float4*)&sW[(ci*3 + 2)*64];
        #pragma unroll
        for (int j4 = 0; j4 < 16; j4++) {
            float4 a = w0[j4], b = w1[j4], c = w2[j4];
            acc[4*j4+0] += a.x*x0 + b.x*x1 + c.x*x2;
            acc[4*j4+1] += a.y*x0 + b.y*x1 + c.y*x2;
            acc[4*j4+2] += a.z*x0 + b.z*x1 + c.z*x2;
            acc[4*j4+3] += a.w*x0 + b.w*x1 + c.w*x2;
        }
    }
    #pragma unroll
    for (int j = 0; j < 64; j++) acc[j] = gelu_exact(acc[j]);

    float oacc[32];
    #pragma unroll
    for (int c = 0; c < 32; c++) oacc[c] = sBp[c];
    #pragma unroll 1
    for (int j = 0; j < 64; j++) {
        float hv = acc[j];
        const float4* wp = (const float4*)&sWp[j*32];
        #pragma unroll
        for (int c4 = 0; c4 < 8; c4++) {
            float4 wv = wp[c4];
            oacc[4*c4+0] += wv.x * hv;
            oacc[4*c4+1] += wv.y * hv;
            oacc[4*c4+2] += wv.z * hv;
            oacc[4*c4+3] += wv.w * hv;
        }
    }
    size_t base = ((size_t)n*T + t0 + tid) * 32;
    #pragma unroll
    for (int c = 0; c < 32; c += 2) {
        __nv_bfloat162 p = __floats2bfloat162_rn(oacc[c]*scale, oacc[c+1]*scale);
        *(__nv_bfloat162*)(&out[base + c]) = p;
    }
}

// ======================= flash attention (warp-level HMMA) ===================
__device__ __forceinline__ unsigned sm_u32(const void* p) {
    return (unsigned)__cvta_generic_to_shared(p);
}
__device__ __forceinline__ void ldm_x4(unsigned &r0, unsigned &r1, unsigned &r2, unsigned &r3, unsigned a) {
    asm volatile("ldmatrix.sync.aligned.m8n8.x4.shared.b16 {%0,%1,%2,%3}, [%4];"
        : "=r"(r0), "=r"(r1), "=r"(r2), "=r"(r3) : "r"(a));
}
__device__ __forceinline__ void ldm_x4_t(unsigned &r0, unsigned &r1, unsigned &r2, unsigned &r3, unsigned a) {
    asm volatile("ldmatrix.sync.aligned.m8n8.x4.trans.shared.b16 {%0,%1,%2,%3}, [%4];"
        : "=r"(r0), "=r"(r1), "=r"(r2), "=r"(r3) : "r"(a));
}
__device__ __forceinline__ void mma16816(float* d,
        unsigned a0, unsigned a1, unsigned a2, unsigned a3,
        unsigned b0, unsigned b1, const float* c) {
    asm volatile("mma.sync.aligned.m16n8k16.row.col.f32.bf16.bf16.f32 "
        "{%0,%1,%2,%3}, {%4,%5,%6,%7}, {%8,%9}, {%10,%11,%12,%13};"
        : "=f"(d[0]), "=f"(d[1]), "=f"(d[2]), "=f"(d[3])
        : "r"(a0), "r"(a1), "r"(a2), "r"(a3), "r"(b0), "r"(b1),
          "f"(c[0]), "f"(c[1]), "f"(c[2]), "f"(c[3]));
}
__device__ __forceinline__ unsigned packbf2(float lo, float hi) {
    __nv_bfloat162 t = __floats2bfloat162_rn(lo, hi);
    return *(unsigned*)&t;
}

// grid: (T/64, nh=2, B*F=32); block 128 (4 warps, 16 q-rows each).
// Softmax in base-2 (log2e folded into q scale). K/V double-buffered in smem.
__global__ void __launch_bounds__(128) attn_kernel()
{
    __shared__ alignas(16) __nv_bfloat16 Qs[64*AP];
    __shared__ alignas(16) __nv_bfloat16 Ks[2][64*AP];
    __shared__ alignas(16) __nv_bfloat16 Vs[2][64*AP];
    const unsigned BUFB = 64*AP*2;             // bytes per K/V buffer
    int bf = blockIdx.z;
    int b  = bf >> 2;
    int h  = blockIdx.y;
    int t0 = blockIdx.x * 64;
    int tid = threadIdx.x, lane = tid & 31, w = tid >> 5;
    int ldrow = tid >> 1, ldhalf = tid & 1;

    // stage Q tile (64 rows x 16 cols of this head)
    *(uint4*)&Qs[ldrow*AP + ldhalf*8] =
        *(const uint4*)&g_q[((size_t)bf*1024 + t0 + ldrow)*32 + h*16 + ldhalf*8];
    __syncthreads();
    unsigned qa0, qa1, qa2, qa3;
    ldm_x4(qa0, qa1, qa2, qa3, sm_u32(&Qs[(w*16 + (lane & 15))*AP + (lane >> 4)*8]));

    float m0 = -1e30f, m1 = -1e30f, l0 = 0.f, l1 = 0.f;
    float o[2][4];
    #pragma unroll
    for (int n = 0; n < 2; n++)
        #pragma unroll
        for (int i = 0; i < 4; i++) o[n][i] = 0.f;

    size_t kvoff = (size_t)b*1024*32 + h*16 + ldhalf*8 + (size_t)ldrow*32;
    unsigned stK = sm_u32(&Ks[0][ldrow*AP + ldhalf*8]);
    unsigned stV = sm_u32(&Vs[0][ldrow*AP + ldhalf*8]);
    unsigned ldK = sm_u32(&Ks[0][(lane & 15)*AP + (lane >> 4)*8]);
    unsigned ldV = sm_u32(&Vs[0][(((lane >> 3) & 1)*8 + (lane & 7))*AP + (lane >> 4)*8]);

    uint4 kreg = *(const uint4*)&g_k[kvoff];
    uint4 vreg = *(const uint4*)&g_v[kvoff];

    #pragma unroll 1
    for (int it = 0; it < 16; it++) {
        unsigned pb = (it & 1) * BUFB;
        asm volatile("st.shared.v4.b32 [%0], {%1,%2,%3,%4};" ::
            "r"(stK + pb), "r"(kreg.x), "r"(kreg.y), "r"(kreg.z), "r"(kreg.w));
        asm volatile("st.shared.v4.b32 [%0], {%1,%2,%3,%4};" ::
            "r"(stV + pb), "r"(vreg.x), "r"(vreg.y), "r"(vreg.z), "r"(vreg.w));
        __syncthreads();
        if (it < 15) {
            kvoff += 64*32;
            kreg = *(const uint4*)&g_k[kvoff];
            vreg = *(const uint4*)&g_v[kvoff];
        }

        // S = Q K^T  (scale * log2e pre-folded into q)
        float sc[8][4];
        #pragma unroll
        for (int nb = 0; nb < 4; nb++) {
            unsigned r0, r1, r2, r3;
            ldm_x4(r0, r1, r2, r3, ldK + pb + nb*(16*AP*2));
            float z[4] = {0.f, 0.f, 0.f, 0.f};
            mma16816(sc[2*nb + 0], qa0, qa1, qa2, qa3, r0, r2, z);
            mma16816(sc[2*nb + 1], qa0, qa1, qa2, qa3, r1, r3, z);
        }
        // online softmax in base-2; regs {0,1} -> row lane/4, {2,3} -> +8
        float nm0 = m0, nm1 = m1;
        #pragma unroll
        for (int t = 0; t < 8; t++) {
            nm0 = fmaxf(nm0, fmaxf(sc[t][0], sc[t][1]));
            nm1 = fmaxf(nm1, fmaxf(sc[t][2], sc[t][3]));
        }
        nm0 = fmaxf(nm0, __shfl_xor_sync(FULL_MASK, nm0, 1));
        nm0 = fmaxf(nm0, __shfl_xor_sync(FULL_MASK, nm0, 2));
        nm1 = fmaxf(nm1, __shfl_xor_sync(FULL_MASK, nm1, 1));
        nm1 = fmaxf(nm1, __shfl_xor_sync(FULL_MASK, nm1, 2));
        float a0 = ex2(m0 - nm0), a1 = ex2(m1 - nm1);
        float rs0 = 0.f, rs1 = 0.f;
        #pragma unroll
        for (int t = 0; t < 8; t++) {
            sc[t][0] = ex2(sc[t][0] - nm0);
            sc[t][1] = ex2(sc[t][1] - nm0);
            sc[t][2] = ex2(sc[t][2] - nm1);
            sc[t][3] = ex2(sc[t][3] - nm1);
            rs0 += sc[t][0] + sc[t][1];
            rs1 += sc[t][2] + sc[t][3];
        }
        rs0 += __shfl_xor_sync(FULL_MASK, rs0, 1);
        rs0 += __shfl_xor_sync(FULL_MASK, rs0, 2);
        rs1 += __shfl_xor_sync(FULL_MASK, rs1, 1);
        rs1 += __shfl_xor_sync(FULL_MASK, rs1, 2);
        l0 = l0*a0 + rs0; l1 = l1*a1 + rs1;
        m0 = nm0; m1 = nm1;
        #pragma unroll
        for (int n = 0; n < 2; n++) {
            o[n][0] *= a0; o[n][1] *= a0; o[n][2] *= a1; o[n][3] *= a1;
        }
        // O += P V  (C-frag -> A-frag repack; V via ldmatrix.trans)
        #pragma unroll
        for (int kb = 0; kb < 4; kb++) {
            unsigned pa0 = packbf2(sc[2*kb][0],   sc[2*kb][1]);
            unsigned pa1 = packbf2(sc[2*kb][2],   sc[2*kb][3]);
            unsigned pa2 = packbf2(sc[2*kb+1][0], sc[2*kb+1][1]);
            unsigned pa3 = packbf2(sc[2*kb+1][2], sc[2*kb+1][3]);
            unsigned v0, v1, v2, v3;
            ldm_x4_t(v0, v1, v2, v3, ldV + pb + kb*(16*AP*2));
            mma16816(o[0], pa0, pa1, pa2, pa3, v0, v1, o[0]);
            mma16816(o[1], pa0, pa1, pa2, pa3, v2, v3, o[1]);
        }
    }
    float inv0 = 1.f / l0, inv1 = 1.f / l1;
    int g = lane >> 2, c2 = (lane & 3) * 2;
    size_t rbase = ((size_t)bf*1024 + t0 + w*16 + g)*32 + h*16;
    #pragma unroll
    for (int n = 0; n < 2; n++) {
        g_y[rbase + n*8 + c2]              = o[n][0]*inv0;
        g_y[rbase + n*8 + c2 + 1]          = o[n][1]*inv0;
        g_y[rbase + 8*32 + n*8 + c2]       = o[n][2]*inv1;
        g_y[rbase + 8*32 + n*8 + c2 + 1]   = o[n][3]*inv1;
    }
}

// ============== epilogue: out = x + y@Wc^T; h=LN(out); out += MLP(h) ========
__global__ void __launch_bounds__(256) epilogue_kernel(
    const float* __restrict__ causal,
    const float* __restrict__ wc,   // [32,32] row-major: wc[c][j]
    const float* __restrict__ lnw,  // [32]
    const float* __restrict__ wfc,  // [32,32]
    const float* __restrict__ wmp,  // [32,32]
    float* __restrict__ out)
{
    __shared__ float sWc[32*32];   // [j][c]
    __shared__ float sWfc[32*32];  // [j][c]
    __shared__ float sWmp[32*32];  // [j][c]
    __shared__ float sLn[32];
    int tid = threadIdx.x, lane = tid & 31, w = tid >> 5;
    for (int i = tid; i < 1024; i += 256) {
        int c = i >> 5, j = i & 31;
        sWc [j*32 + c] = wc[i];
        sWfc[j*32 + c] = wfc[i];
        sWmp[j*32 + c] = wmp[i];
    }
    if (tid < 32) sLn[tid] = lnw[tid];
    __syncthreads();

    const int NROWS = 32 * 1024;
    for (int row = blockIdx.x * 8 + w; row < NROWS; row += gridDim.x * 8) {
        float yv = g_y[(size_t)row*32 + lane];
        float cp = 0.f;
        #pragma unroll
        for (int j = 0; j < 32; j++)
            cp += sWc[j*32 + lane] * __shfl_sync(FULL_MASK, yv, j);
        float ov = causal[(size_t)row*32 + lane] + cp;

        float mu = ov;
        #pragma unroll
        for (int m = 16; m >= 1; m >>= 1) mu += __shfl_xor_sync(FULL_MASK, mu, m);
        mu *= (1.f/32.f);
        float d = ov - mu;
        float var = d*d;
        #pragma unroll
        for (int m = 16; m >= 1; m >>= 1) var += __shfl_xor_sync(FULL_MASK, var, m);
        var *= (1.f/32.f);
        float hn = d * rsqrtf(var + 1e-5f) * sLn[lane];

        float fcv = 0.f;
        #pragma unroll
        for (int j = 0; j < 32; j++)
            fcv += sWfc[j*32 + lane] * __shfl_sync(FULL_MASK, hn, j);
        fcv = gelu_exact(fcv);

        float mp = 0.f;
        #pragma unroll
        for (int j = 0; j < 32; j++)
            mp += sWmp[j*32 + lane] * __shfl_sync(FULL_MASK, fcv, j);

        out[(size_t)row*32 + lane] = ov + mp;
    }
}

// ============================= launch ========================================
extern "C" void kernel_launch(void* const* d_in, const int* in_sizes, int n_in,
                              void* d_out, int out_size) {
    (void)in_sizes; (void)n_in; (void)out_size;
    const float* causal = (const float*)d_in[0];
    const float* past   = (const float*)d_in[1];

    tcl_all_kernel<<<dim3(16, 48), 64>>>(causal, past,
        (const float*)d_in[2],  (const float*)d_in[3],
        (const float*)d_in[4],  (const float*)d_in[5],
        (const float*)d_in[6],  (const float*)d_in[7],
        (const float*)d_in[8],  (const float*)d_in[9],
        (const float*)d_in[10], (const float*)d_in[11],
        (const float*)d_in[12], (const float*)d_in[13]);

    attn_kernel<<<dim3(16, 2, 32), 128>>>();

    epilogue_kernel<<<1024, 256>>>(causal,
        (const float*)d_in[14], (const float*)d_in[15],
        (const float*)d_in[16], (const float*)d_in[17],
        (float*)d_out);
}

// round 9
// speedup vs baseline: 2.6906x; 2.6906x over previous
#include <cuda_runtime.h>
#include <cuda_bf16.h>
#include <math.h>

#define FULL_MASK 0xffffffffu
#define AP 24   // smem row pitch in bf16 elems (48B) -> conflict-free ldmatrix

// ---------------- scratch (__device__ globals; no runtime allocation) -------
__device__ __align__(16) __nv_bfloat16 g_q[32u*1024u*32u];  // [bf][t][c], pre-scaled by 0.25*log2(e)
__device__ __align__(16) __nv_bfloat16 g_k[8u*1024u*32u];   // [b][s][c]
__device__ __align__(16) __nv_bfloat16 g_v[8u*1024u*32u];   // [b][s][c]
__device__ __align__(16) float          g_y[32u*1024u*32u]; // attention output, fp32

__device__ __forceinline__ float gelu_exact(float v) {
    return 0.5f * v * (1.f + erff(v * 0.70710678118654752440f));
}
__device__ __forceinline__ float ex2(float x) {
    float y; asm("ex2.approx.f32 %0, %1;" : "=f"(y) : "f"(x)); return y;
}

// ======================= merged TCL for q, k, v ==============================
// grid (8, 48): y<32 -> q (causal seq y), y<40 -> k (past seq y-32), else v.
// Block 128 threads = 128 timesteps. Conv channels computed in 4 chunks of 16
// to keep live registers ~75 (R8's acc[64] version hit 162 regs, occ 14.8%).
__global__ void __launch_bounds__(128) tcl_all_kernel(
    const float* __restrict__ causal, const float* __restrict__ past,
    const float* __restrict__ wq_c, const float* __restrict__ bq_c,
    const float* __restrict__ wq_p, const float* __restrict__ bq_p,
    const float* __restrict__ wk_c, const float* __restrict__ bk_c,
    const float* __restrict__ wk_p, const float* __restrict__ bk_p,
    const float* __restrict__ wv_c, const float* __restrict__ bv_c,
    const float* __restrict__ wv_p, const float* __restrict__ bv_p)
{
    __shared__ alignas(16) float sW[32*3*64];   // [ci][k][j] (j contiguous)
    __shared__ alignas(16) float sWp[64*32];    // [j][c]     (c contiguous)
    __shared__ float sB[64];
    __shared__ float sBp[32];
    __shared__ alignas(16) float sx[130][33];   // pitch 33 -> conflict-free column reads
    const int T = 1024;
    int ny = blockIdx.y, t0 = blockIdx.x * 128, tid = threadIdx.x;

    const float *x, *wconv, *bconv, *wproj, *bproj;
    __nv_bfloat16* out;
    float scale;
    int n;
    if (ny < 32) {
        x = causal; n = ny; out = g_q;
        wconv = wq_c; bconv = bq_c; wproj = wq_p; bproj = bq_p;
        scale = 0.36067376022224085f;   // (1/sqrt(16)) * log2(e)
    } else if (ny < 40) {
        x = past; n = ny - 32; out = g_k;
        wconv = wk_c; bconv = bk_c; wproj = wk_p; bproj = bk_p;
        scale = 1.0f;
    } else {
        x = past; n = ny - 40; out = g_v;
        wconv = wv_c; bconv = bv_c; wproj = wv_p; bproj = bv_p;
        scale = 1.0f;
    }

    for (int i = tid; i < 6144; i += 128) {
        int j = i / 96, r = i - j * 96, ci = r / 3, kk = r - ci * 3;
        sW[(ci*3 + kk)*64 + j] = wconv[i];
    }
    for (int i = tid; i < 2048; i += 128) {
        int c = i >> 6, j = i & 63;
        sWp[j*32 + c] = wproj[i];
    }
    if (tid < 64) sB[tid] = bconv[tid];
    if (tid >= 64 && tid < 96) sBp[tid - 64] = bproj[tid - 64];
    for (int i = tid; i < 130*32; i += 128) {
        int r = i >> 5, c = i & 31;
        int t = t0 - 2 + r;
        sx[r][c] = (t >= 0) ? x[((size_t)n*T + t)*32 + c] : 0.f;
    }
    __syncthreads();

    float oacc[32];
    #pragma unroll
    for (int c = 0; c < 32; c++) oacc[c] = sBp[c];

    #pragma unroll 1
    for (int ch = 0; ch < 4; ch++) {
        float acc[16];
        #pragma unroll
        for (int jj = 0; jj < 16; jj++) acc[jj] = sB[ch*16 + jj];

        #pragma unroll 1
        for (int ci = 0; ci < 32; ci++) {
            float x0 = sx[tid + 0][ci];
            float x1 = sx[tid + 1][ci];
            float x2 = sx[tid + 2][ci];
            const float4* w0 = (const float4*)&sW[(ci*3 + 0)*64 + ch*16];
            const float4* w1 = (const float4*)&sW[(ci*3 + 1)*64 + ch*16];
            const float4* w2 = (const float4*)&sW[(ci*3 + 2)*64 + ch*16];
            #pragma unroll
            for (int j4 = 0; j4 < 4; j4++) {
                float4 a = w0[j4], b = w1[j4], c = w2[j4];
                acc[4*j4+0] += a.x*x0 + b.x*x1 + c.x*x2;
                acc[4*j4+1] += a.y*x0 + b.y*x1 + c.y*x2;
                acc[4*j4+2] += a.z*x0 + b.z*x1 + c.z*x2;
                acc[4*j4+3] += a.w*x0 + b.w*x1 + c.w*x2;
            }
        }
        #pragma unroll
        for (int jj = 0; jj < 16; jj++) {
            float hv = gelu_exact(acc[jj]);
            const float4* wp = (const float4*)&sWp[(ch*16 + jj)*32];
            #pragma unroll
            for (int c4 = 0; c4 < 8; c4++) {
                float4 wv = wp[c4];
                oacc[4*c4+0] += wv.x * hv;
                oacc[4*c4+1] += wv.y * hv;
                oacc[4*c4+2] += wv.z * hv;
                oacc[4*c4+3] += wv.w * hv;
            }
        }
    }
    size_t base = ((size_t)n*T + t0 + tid) * 32;
    #pragma unroll
    for (int c = 0; c < 32; c += 2) {
        __nv_bfloat162 p = __floats2bfloat162_rn(oacc[c]*scale, oacc[c+1]*scale);
        *(__nv_bfloat162*)(&out[base + c]) = p;
    }
}

// ======================= flash attention (warp-level HMMA) ===================
__device__ __forceinline__ unsigned sm_u32(const void* p) {
    return (unsigned)__cvta_generic_to_shared(p);
}
__device__ __forceinline__ void ldm_x4(unsigned &r0, unsigned &r1, unsigned &r2, unsigned &r3, unsigned a) {
    asm volatile("ldmatrix.sync.aligned.m8n8.x4.shared.b16 {%0,%1,%2,%3}, [%4];"
        : "=r"(r0), "=r"(r1), "=r"(r2), "=r"(r3) : "r"(a));
}
__device__ __forceinline__ void ldm_x4_t(unsigned &r0, unsigned &r1, unsigned &r2, unsigned &r3, unsigned a) {
    asm volatile("ldmatrix.sync.aligned.m8n8.x4.trans.shared.b16 {%0,%1,%2,%3}, [%4];"
        : "=r"(r0), "=r"(r1), "=r"(r2), "=r"(r3) : "r"(a));
}
__device__ __forceinline__ void mma16816(float* d,
        unsigned a0, unsigned a1, unsigned a2, unsigned a3,
        unsigned b0, unsigned b1, const float* c) {
    asm volatile("mma.sync.aligned.m16n8k16.row.col.f32.bf16.bf16.f32 "
        "{%0,%1,%2,%3}, {%4,%5,%6,%7}, {%8,%9}, {%10,%11,%12,%13};"
        : "=f"(d[0]), "=f"(d[1]), "=f"(d[2]), "=f"(d[3])
        : "r"(a0), "r"(a1), "r"(a2), "r"(a3), "r"(b0), "r"(b1),
          "f"(c[0]), "f"(c[1]), "f"(c[2]), "f"(c[3]));
}
__device__ __forceinline__ unsigned packbf2(float lo, float hi) {
    __nv_bfloat162 t = __floats2bfloat162_rn(lo, hi);
    return *(unsigned*)&t;
}

// grid: (T/64, nh=2, B*F=32); block 128 (4 warps, 16 q-rows each).
// Softmax in base-2 (log2e folded into q scale). K/V double-buffered in smem.
__global__ void __launch_bounds__(128) attn_kernel()
{
    __shared__ alignas(16) __nv_bfloat16 Qs[64*AP];
    __shared__ alignas(16) __nv_bfloat16 Ks[2][64*AP];
    __shared__ alignas(16) __nv_bfloat16 Vs[2][64*AP];
    const unsigned BUFB = 64*AP*2;             // bytes per K/V buffer
    int bf = blockIdx.z;
    int b  = bf >> 2;
    int h  = blockIdx.y;
    int t0 = blockIdx.x * 64;
    int tid = threadIdx.x, lane = tid & 31, w = tid >> 5;
    int ldrow = tid >> 1, ldhalf = tid & 1;

    // stage Q tile (64 rows x 16 cols of this head)
    *(uint4*)&Qs[ldrow*AP + ldhalf*8] =
        *(const uint4*)&g_q[((size_t)bf*1024 + t0 + ldrow)*32 + h*16 + ldhalf*8];
    __syncthreads();
    unsigned qa0, qa1, qa2, qa3;
    ldm_x4(qa0, qa1, qa2, qa3, sm_u32(&Qs[(w*16 + (lane & 15))*AP + (lane >> 4)*8]));

    float m0 = -1e30f, m1 = -1e30f, l0 = 0.f, l1 = 0.f;
    float o[2][4];
    #pragma unroll
    for (int n = 0; n < 2; n++)
        #pragma unroll
        for (int i = 0; i < 4; i++) o[n][i] = 0.f;

    size_t kvoff = (size_t)b*1024*32 + h*16 + ldhalf*8 + (size_t)ldrow*32;
    unsigned stK = sm_u32(&Ks[0][ldrow*AP + ldhalf*8]);
    unsigned stV = sm_u32(&Vs[0][ldrow*AP + ldhalf*8]);
    unsigned ldK = sm_u32(&Ks[0][(lane & 15)*AP + (lane >> 4)*8]);
    unsigned ldV = sm_u32(&Vs[0][(((lane >> 3) & 1)*8 + (lane & 7))*AP + (lane >> 4)*8]);

    uint4 kreg = *(const uint4*)&g_k[kvoff];
    uint4 vreg = *(const uint4*)&g_v[kvoff];

    #pragma unroll 1
    for (int it = 0; it < 16; it++) {
        unsigned pb = (it & 1) * BUFB;
        asm volatile("st.shared.v4.b32 [%0], {%1,%2,%3,%4};" ::
            "r"(stK + pb), "r"(kreg.x), "r"(kreg.y), "r"(kreg.z), "r"(kreg.w));
        asm volatile("st.shared.v4.b32 [%0], {%1,%2,%3,%4};" ::
            "r"(stV + pb), "r"(vreg.x), "r"(vreg.y), "r"(vreg.z), "r"(vreg.w));
        __syncthreads();
        if (it < 15) {
            kvoff += 64*32;
            kreg = *(const uint4*)&g_k[kvoff];
            vreg = *(const uint4*)&g_v[kvoff];
        }

        // S = Q K^T  (scale * log2e pre-folded into q)
        float sc[8][4];
        #pragma unroll
        for (int nb = 0; nb < 4; nb++) {
            unsigned r0, r1, r2, r3;
            ldm_x4(r0, r1, r2, r3, ldK + pb + nb*(16*AP*2));
            float z[4] = {0.f, 0.f, 0.f, 0.f};
            mma16816(sc[2*nb + 0], qa0, qa1, qa2, qa3, r0, r2, z);
            mma16816(sc[2*nb + 1], qa0, qa1, qa2, qa3, r1, r3, z);
        }
        // online softmax in base-2; regs {0,1} -> row lane/4, {2,3} -> +8
        float nm0 = m0, nm1 = m1;
        #pragma unroll
        for (int t = 0; t < 8; t++) {
            nm0 = fmaxf(nm0, fmaxf(sc[t][0], sc[t][1]));
            nm1 = fmaxf(nm1, fmaxf(sc[t][2], sc[t][3]));
        }
        nm0 = fmaxf(nm0, __shfl_xor_sync(FULL_MASK, nm0, 1));
        nm0 = fmaxf(nm0, __shfl_xor_sync(FULL_MASK, nm0, 2));
        nm1 = fmaxf(nm1, __shfl_xor_sync(FULL_MASK, nm1, 1));
        nm1 = fmaxf(nm1, __shfl_xor_sync(FULL_MASK, nm1, 2));
        float a0 = ex2(m0 - nm0), a1 = ex2(m1 - nm1);
        float rs0 = 0.f, rs1 = 0.f;
        #pragma unroll
        for (int t = 0; t < 8; t++) {
            sc[t][0] = ex2(sc[t][0] - nm0);
            sc[t][1] = ex2(sc[t][1] - nm0);
            sc[t][2] = ex2(sc[t][2] - nm1);
            sc[t][3] = ex2(sc[t][3] - nm1);
            rs0 += sc[t][0] + sc[t][1];
            rs1 += sc[t][2] + sc[t][3];
        }
        rs0 += __shfl_xor_sync(FULL_MASK, rs0, 1);
        rs0 += __shfl_xor_sync(FULL_MASK, rs0, 2);
        rs1 += __shfl_xor_sync(FULL_MASK, rs1, 1);
        rs1 += __shfl_xor_sync(FULL_MASK, rs1, 2);
        l0 = l0*a0 + rs0; l1 = l1*a1 + rs1;
        m0 = nm0; m1 = nm1;
        #pragma unroll
        for (int n = 0; n < 2; n++) {
            o[n][0] *= a0; o[n][1] *= a0; o[n][2] *= a1; o[n][3] *= a1;
        }
        // O += P V  (C-frag -> A-frag repack; V via ldmatrix.trans)
        #pragma unroll
        for (int kb = 0; kb < 4; kb++) {
            unsigned pa0 = packbf2(sc[2*kb][0],   sc[2*kb][1]);
            unsigned pa1 = packbf2(sc[2*kb][2],   sc[2*kb][3]);
            unsigned pa2 = packbf2(sc[2*kb+1][0], sc[2*kb+1][1]);
            unsigned pa3 = packbf2(sc[2*kb+1][2], sc[2*kb+1][3]);
            unsigned v0, v1, v2, v3;
            ldm_x4_t(v0, v1, v2, v3, ldV + pb + kb*(16*AP*2));
            mma16816(o[0], pa0, pa1, pa2, pa3, v0, v1, o[0]);
            mma16816(o[1], pa0, pa1, pa2, pa3, v2, v3, o[1]);
        }
    }
    float inv0 = 1.f / l0, inv1 = 1.f / l1;
    int g = lane >> 2, c2 = (lane & 3) * 2;
    size_t rbase = ((size_t)bf*1024 + t0 + w*16 + g)*32 + h*16;
    #pragma unroll
    for (int n = 0; n < 2; n++) {
        g_y[rbase + n*8 + c2]              = o[n][0]*inv0;
        g_y[rbase + n*8 + c2 + 1]          = o[n][1]*inv0;
        g_y[rbase + 8*32 + n*8 + c2]       = o[n][2]*inv1;
        g_y[rbase + 8*32 + n*8 + c2 + 1]   = o[n][3]*inv1;
    }
}

// ============== epilogue: out = x + y@Wc^T; h=LN(out); out += MLP(h) ========
// One thread per row (32 channels in registers); weights broadcast from smem.
__global__ void __launch_bounds__(128) epilogue_kernel(
    const float* __restrict__ causal,
    const float* __restrict__ wc,   // [32,32] row-major: wc[c][j]
    const float* __restrict__ lnw,  // [32]
    const float* __restrict__ wfc,  // [32,32] row-major: wfc[j][i]
    const float* __restrict__ wmp,  // [32,32] row-major: wmp[c][j]
    float* __restrict__ out)
{
    __shared__ alignas(16) float sWc[1024];    // [c][j] as given
    __shared__ alignas(16) float sWfc[1024];   // [j][i] as given
    __shared__ alignas(16) float sWmpT[1024];  // transposed: [j][c]
    __shared__ float sLn[32];
    int tid = threadIdx.x;
    for (int i = tid; i < 1024; i += 128) {
        sWc[i]  = wc[i];
        sWfc[i] = wfc[i];
        int c = i >> 5, j = i & 31;
        sWmpT[j*32 + c] = wmp[i];
    }
    if (tid < 32) sLn[tid] = lnw[tid];
    __syncthreads();

    size_t row = (size_t)blockIdx.x * 128 + tid;
    const float4* yrow = (const float4*)&g_y[row*32];
    const float4* xrow = (const float4*)&causal[row*32];

    float y[32], ov[32];
    #pragma unroll
    for (int i = 0; i < 8; i++) {
        float4 t = yrow[i];
        y[4*i] = t.x; y[4*i+1] = t.y; y[4*i+2] = t.z; y[4*i+3] = t.w;
    }
    // cproj: ov[c] = sum_j y[j] * wc[c][j]
    #pragma unroll
    for (int c = 0; c < 32; c++) {
        const float4* wr = (const float4*)&sWc[c*32];
        float acc = 0.f;
        #pragma unroll
        for (int j4 = 0; j4 < 8; j4++) {
            float4 wv = wr[j4];
            acc += wv.x*y[4*j4] + wv.y*y[4*j4+1] + wv.z*y[4*j4+2] + wv.w*y[4*j4+3];
        }
        ov[c] = acc;
    }
    // residual
    #pragma unroll
    for (int i = 0; i < 8; i++) {
        float4 t = xrow[i];
        ov[4*i] += t.x; ov[4*i+1] += t.y; ov[4*i+2] += t.z; ov[4*i+3] += t.w;
    }
    // layernorm -> h (reuse y)
    float mu = 0.f;
    #pragma unroll
    for (int c = 0; c < 32; c++) mu += ov[c];
    mu *= (1.f/32.f);
    float var = 0.f;
    #pragma unroll
    for (int c = 0; c < 32; c++) { float d = ov[c] - mu; var += d*d; }
    float rstd = rsqrtf(var*(1.f/32.f) + 1e-5f);
    #pragma unroll
    for (int c = 0; c < 32; c++) y[c] = (ov[c] - mu) * rstd * sLn[c];
    // fc + gelu, then accumulate mlp proj directly into ov via transposed wmp
    #pragma unroll
    for (int j = 0; j < 32; j++) {
        const float4* wr = (const float4*)&sWfc[j*32];
        float acc = 0.f;
        #pragma unroll
        for (int i4 = 0; i4 < 8; i4++) {
            float4 wv = wr[i4];
            acc += wv.x*y[4*i4] + wv.y*y[4*i4+1] + wv.z*y[4*i4+2] + wv.w*y[4*i4+3];
        }
        float gv = gelu_exact(acc);
        const float4* wm = (const float4*)&sWmpT[j*32];
        #pragma unroll
        for (int c4 = 0; c4 < 8; c4++) {
            float4 wv = wm[c4];
            ov[4*c4+0] += wv.x * gv;
            ov[4*c4+1] += wv.y * gv;
            ov[4*c4+2] += wv.z * gv;
            ov[4*c4+3] += wv.w * gv;
        }
    }
    float4* orow = (float4*)&out[row*32];
    #pragma unroll
    for (int i = 0; i < 8; i++) {
        float4 t;
        t.x = ov[4*i]; t.y = ov[4*i+1]; t.z = ov[4*i+2]; t.w = ov[4*i+3];
        orow[i] = t;
    }
}

// ============================= launch ========================================
extern "C" void kernel_launch(void* const* d_in, const int* in_sizes, int n_in,
                              void* d_out, int out_size) {
    (void)in_sizes; (void)n_in; (void)out_size;
    const float* causal = (const float*)d_in[0];
    const float* past   = (const float*)d_in[1];

    tcl_all_kernel<<<dim3(8, 48), 128>>>(causal, past,
        (const float*)d_in[2],  (const float*)d_in[3],
        (const float*)d_in[4],  (const float*)d_in[5],
        (const float*)d_in[6],  (const float*)d_in[7],
        (const float*)d_in[8],  (const float*)d_in[9],
        (const float*)d_in[10], (const float*)d_in[11],
        (const float*)d_in[12], (const float*)d_in[13]);

    attn_kernel<<<dim3(16, 2, 32), 128>>>();

    epilogue_kernel<<<256, 128>>>(causal,
        (const float*)d_in[14], (const float*)d_in[15],
        (const float*)d_in[16], (const float*)d_in[17],
        (float*)d_out);
}